// round 4
// baseline (speedup 1.0000x reference)
#include <cuda_runtime.h>
#include <cuda_bf16.h>

#define BB 16
#define NN 256
#define DD 512
#define PE_ROWS 64   // pos = t - start < x[b,seg] <= 63, so only rows 0..63 are gathered

// Single persistent kernel.
// Each CTA stages pos_enc rows 0..63 (128 KB) + per-batch cumsum (16 KB) in smem.
// Warps own CONTIGUOUS row ranges: binary search once, then monotone segment
// advance (1 smem broadcast per row). Streaming 128-bit stores.
__global__ __launch_bounds__(1024, 1)
void pe_gather_kernel(const int* __restrict__ x,
                      const float* __restrict__ pos_enc,
                      float* __restrict__ out, int T, int chunk) {
    extern __shared__ float smem[];
    float* s_pe  = smem;                                // PE_ROWS * DD floats (128 KB)
    int*   s_cum = (int*)(smem + PE_ROWS * DD);         // BB * NN ints (16 KB)

    const int warp = threadIdx.x >> 5;
    const int lane = threadIdx.x & 31;

    // ---- stage hot pos_enc rows ----
    {
        const float4* src = (const float4*)pos_enc;
        float4* dst = (float4*)s_pe;
        for (int i = threadIdx.x; i < PE_ROWS * DD / 4; i += blockDim.x)
            dst[i] = src[i];
    }

    // ---- per-CTA cumsum of x: warps 0..15 each scan one batch row ----
    if (warp < BB) {
        int carry = 0;
        for (int c = 0; c < NN / 32; c++) {
            int idx = c * 32 + lane;
            int v = x[warp * NN + idx];
            #pragma unroll
            for (int off = 1; off < 32; off <<= 1) {
                int n = __shfl_up_sync(0xffffffffu, v, off);
                if (lane >= off) v += n;
            }
            v += carry;
            s_cum[warp * NN + idx] = v;
            carry = __shfl_sync(0xffffffffu, v, 31);
        }
    }
    __syncthreads();

    // ---- contiguous row range for this warp ----
    const long total = (long)BB * T;
    const int warp_global = blockIdx.x * (blockDim.x >> 5) + warp;
    long r0 = (long)warp_global * chunk;
    if (r0 >= total) return;
    long r1 = r0 + chunk; if (r1 > total) r1 = total;

    int b = (int)(r0 / T);            // only division in the kernel
    int t = (int)(r0 - (long)b * T);
    const int* cum = s_cum + b * NN;
    int last = cum[NN - 1];

    // initial searchsorted(cum, t, 'right'): first seg with cum[seg] > t
    int seg;
    {
        int lo = 0, hi = NN;
        #pragma unroll
        for (int it = 0; it < 9; it++) {
            if (lo < hi) {
                int mid = (lo + hi) >> 1;
                if (cum[mid] <= t) lo = mid + 1; else hi = mid;
            }
        }
        seg = lo;
    }

    const float4 z = make_float4(0.f, 0.f, 0.f, 0.f);

    for (long r = r0; r < r1; r++) {
        float4* dst = (float4*)(out + r * (long)DD);

        if (t >= last) {
            #pragma unroll
            for (int i = 0; i < 4; i++) __stcs(dst + lane + 32 * i, z);
        } else {
            // monotone advance (also skips zero-length segments)
            while (cum[seg] <= t) seg++;
            const int start = (seg > 0) ? cum[seg - 1] : 0;
            const int pos = t - start;                   // in [0, 62]
            const float4* src = (const float4*)(s_pe + pos * DD);
            float4 v0 = src[lane +  0];
            float4 v1 = src[lane + 32];
            float4 v2 = src[lane + 64];
            float4 v3 = src[lane + 96];
            __stcs(dst + lane +  0, v0);
            __stcs(dst + lane + 32, v1);
            __stcs(dst + lane + 64, v2);
            __stcs(dst + lane + 96, v3);
        }

        // advance t; on batch-row boundary, reload tables ONLY if another
        // batch row exists (b can hit BB on the very last row of a chunk —
        // dereferencing then reads past the smem allocation).
        if (++t == T) {
            t = 0; b++;
            if (b < BB) { cum += NN; last = cum[NN - 1]; seg = 0; }
            else break;   // no rows beyond batch BB-1 in any valid chunk
        }
    }
}

extern "C" void kernel_launch(void* const* d_in, const int* in_sizes, int n_in,
                              void* d_out, int out_size) {
    const int*   x       = (const int*)d_in[0];
    const float* pos_enc = (const float*)d_in[1];
    float*       out     = (float*)d_out;

    const int T = out_size / (BB * DD);

    int sms = 148;
    cudaDeviceGetAttribute(&sms, cudaDevAttrMultiProcessorCount, 0);

    const long total = (long)BB * T;
    const int nwarps = sms * 32;
    const int chunk = (int)((total + nwarps - 1) / nwarps);

    const size_t smem_bytes = (size_t)(PE_ROWS * DD) * sizeof(float)
                            + (size_t)(BB * NN) * sizeof(int);   // 147456 B
    cudaFuncSetAttribute(pe_gather_kernel,
                         cudaFuncAttributeMaxDynamicSharedMemorySize,
                         (int)smem_bytes);
    pe_gather_kernel<<<sms, 1024, smem_bytes>>>(x, pos_enc, out, T, chunk);
}